// round 9
// baseline (speedup 1.0000x reference)
#include <cuda_runtime.h>
#include <cuda_bf16.h>
#include <cstdint>

#define N_VARS_MAX    1000000
#define N_CONSTRS_MAX 500000

// Zero-initialized at module load; reduce_kernel restores zeros after each use,
// so every kernel_launch call sees ax == 0 (graph-replay safe, deterministic).
__device__ float        g_ax[N_CONSTRS_MAX];
__device__ double       g_sum;          // reset by last reduce block each call
__device__ unsigned int g_done;         // wraps back to 0 via atomicInc

// ---------------------------------------------------------------------------
// Kernel 1: fused sigmoid + scatter (unchanged from R8 — at its L2 floor).
// ---------------------------------------------------------------------------
__device__ __forceinline__ void red_add_f32(float* addr, float val)
{
    asm volatile("red.global.add.f32 [%0], %1;" :: "l"(addr), "f"(val) : "memory");
}

__device__ __forceinline__ float sigmoidf_fast(float x)
{
    return 1.0f / (1.0f + __expf(-x));
}

__global__ __launch_bounds__(256, 8) void scatter_kernel(
    const float* __restrict__ pred,
    const int*   __restrict__ constr_idx,
    const int*   __restrict__ var_idx,
    const float* __restrict__ coeff,
    int nnz)
{
    int nvec = nnz >> 2;
    int i = blockIdx.x * blockDim.x + threadIdx.x;
    if (i < nvec) {
        int4   ci = reinterpret_cast<const int4*>(constr_idx)[i];
        int4   vi = reinterpret_cast<const int4*>(var_idx)[i];
        float4 co = reinterpret_cast<const float4*>(coeff)[i];

        float x0 = __ldg(&pred[vi.x]);
        float x1 = __ldg(&pred[vi.y]);
        float x2 = __ldg(&pred[vi.z]);
        float x3 = __ldg(&pred[vi.w]);

        red_add_f32(&g_ax[ci.x], co.x * sigmoidf_fast(x0));
        red_add_f32(&g_ax[ci.y], co.y * sigmoidf_fast(x1));
        red_add_f32(&g_ax[ci.z], co.z * sigmoidf_fast(x2));
        red_add_f32(&g_ax[ci.w], co.w * sigmoidf_fast(x3));
    }
    if (i == 0) {
        for (int j = nvec << 2; j < nnz; j++)
            red_add_f32(&g_ax[constr_idx[j]],
                        coeff[j] * sigmoidf_fast(__ldg(&pred[var_idx[j]])));
    }
}

// ---------------------------------------------------------------------------
// Violation helper
// ---------------------------------------------------------------------------
__device__ __forceinline__ float viol(float ax, float r, int s)
{
    float d = ax - r;
    return (s == 1) ? fmaxf(d, 0.f)
         : (s == 2) ? fmaxf(-d, 0.f)
         : (s == 3) ? fabsf(d) : 0.f;
}

// ---------------------------------------------------------------------------
// Kernel 2: violations + reduce + finalize + RESTORE.
// TWO float4-triples per thread (block-tiled): 6 loads issued before any
// compute/store -> double the in-flight memory per thread vs R8 (reduce was
// latency-bound at occ=42%, issue=12%, DRAM=10%).
// ---------------------------------------------------------------------------
__global__ __launch_bounds__(512) void reduce_kernel(
    const float* __restrict__ rhs,
    const int*   __restrict__ sense,
    int n_constrs,
    float* __restrict__ out,
    int n_blocks)
{
    int nc4 = n_constrs >> 2;
    // block-tiled: block b owns float4 range [b*1024, b*1024+1024)
    int i0 = blockIdx.x * (int)blockDim.x * 2 + threadIdx.x;
    int i1 = i0 + (int)blockDim.x;

    const float4 zero4 = make_float4(0.f, 0.f, 0.f, 0.f);
    float local = 0.0f;

    bool a0 = (i0 < nc4), a1 = (i1 < nc4);
    float4 ax0, r0; int4 s0;
    float4 ax1, r1; int4 s1;

    // issue all loads first (MLP = up to 6 per thread)
    if (a0) {
        ax0 = reinterpret_cast<const float4*>(g_ax)[i0];
        r0  = reinterpret_cast<const float4*>(rhs)[i0];
        s0  = reinterpret_cast<const int4*>(sense)[i0];
    }
    if (a1) {
        ax1 = reinterpret_cast<const float4*>(g_ax)[i1];
        r1  = reinterpret_cast<const float4*>(rhs)[i1];
        s1  = reinterpret_cast<const int4*>(sense)[i1];
    }

    if (a0) {
        local += viol(ax0.x, r0.x, s0.x) + viol(ax0.y, r0.y, s0.y)
               + viol(ax0.z, r0.z, s0.z) + viol(ax0.w, r0.w, s0.w);
        reinterpret_cast<float4*>(g_ax)[i0] = zero4;
    }
    if (a1) {
        local += viol(ax1.x, r1.x, s1.x) + viol(ax1.y, r1.y, s1.y)
               + viol(ax1.z, r1.z, s1.z) + viol(ax1.w, r1.w, s1.w);
        reinterpret_cast<float4*>(g_ax)[i1] = zero4;
    }

    // scalar tail (n_constrs % 4), also restores zeros
    if (blockIdx.x == 0 && threadIdx.x == 0) {
        for (int j = nc4 << 2; j < n_constrs; j++) {
            float d = g_ax[j] - rhs[j];
            g_ax[j] = 0.0f;
            local += viol(d + rhs[j], rhs[j], sense[j]);
        }
    }

    // warp reduce
    #pragma unroll
    for (int off = 16; off > 0; off >>= 1)
        local += __shfl_xor_sync(0xFFFFFFFFu, local, off);

    __shared__ float warp_sums[32];
    int lane = threadIdx.x & 31;
    int wid  = threadIdx.x >> 5;
    if (lane == 0) warp_sums[wid] = local;
    __syncthreads();
    int nwarps = blockDim.x >> 5;

    __shared__ bool is_last;
    if (wid == 0) {
        float b = (lane < nwarps) ? warp_sums[lane] : 0.0f;
        #pragma unroll
        for (int off = 16; off > 0; off >>= 1)
            b += __shfl_xor_sync(0xFFFFFFFFu, b, off);
        if (lane == 0) {
            atomicAdd(&g_sum, (double)b);
            __threadfence();
            unsigned int ticket = atomicInc(&g_done, (unsigned int)(n_blocks - 1));
            is_last = (ticket == (unsigned int)(n_blocks - 1));
        }
    }
    __syncthreads();
    if (is_last && threadIdx.x == 0) {
        out[0] = (float)(g_sum / (double)n_constrs);
        g_sum = 0.0;
    }
}

// ---------------------------------------------------------------------------
// Launch: two kernels.
// ---------------------------------------------------------------------------
extern "C" void kernel_launch(void* const* d_in, const int* in_sizes, int n_in,
                              void* d_out, int out_size)
{
    const float* pred       = (const float*)d_in[0];
    const int*   constr_idx = (const int*)  d_in[1];
    const int*   var_idx    = (const int*)  d_in[2];
    const float* coeff      = (const float*)d_in[3];
    const float* rhs        = (const float*)d_in[4];
    const int*   sense      = (const int*)  d_in[5];

    int nnz       = in_sizes[1];
    int n_constrs = in_sizes[4];

    // 1) fused sigmoid + scatter
    {
        int threads = 256;
        int nvec    = nnz >> 2;
        int blocks  = (nvec + threads - 1) / threads;
        if (blocks < 1) blocks = 1;
        scatter_kernel<<<blocks, threads>>>(pred, constr_idx, var_idx, coeff, nnz);
    }

    // 2) reduce + finalize + state restore — 2 float4 per thread
    {
        int threads = 512;
        int work    = n_constrs >> 2;                 // float4 count
        int per_blk = threads * 2;
        int blocks  = (work + per_blk - 1) / per_blk;
        if (blocks < 1) blocks = 1;
        reduce_kernel<<<blocks, threads>>>(rhs, sense, n_constrs, (float*)d_out, blocks);
    }
}